// round 15
// baseline (speedup 1.0000x reference)
#include <cuda_runtime.h>
#include <cuda_fp16.h>
#include <cstdint>
#include <cstddef>

#define FDIM   1024
#define HD3    3072
#define NHEADS 16
#define DHEAD  64
#define MTOK   4096
#define SEQ    2048

// ---------------------------------------------------------------------------
// Scratch (__device__ globals per allocation rules)
// ---------------------------------------------------------------------------
__device__ __half g_xh    [(size_t)MTOK * FDIM];
__device__ __half g_wqkvh [(size_t)HD3  * FDIM];
__device__ __half g_wprojh[(size_t)FDIM * FDIM];
__device__ __half g_qkvh  [(size_t)MTOK * HD3];
__device__ __half g_aoh   [(size_t)MTOK * FDIM];

// ---------------------------------------------------------------------------
// Helpers: base-sm_103-safe ISA only (mma.sync / ldmatrix / cp.async)
// ---------------------------------------------------------------------------
__device__ __forceinline__ uint32_t smem_to_u32(const void* p) {
    uint32_t a;
    asm("{ .reg .u64 t; cvta.to.shared.u64 t, %1; cvt.u32.u64 %0, t; }" : "=r"(a) : "l"(p));
    return a;
}

#define SWZ(off) ((uint32_t)(off) ^ ((((uint32_t)(off)) >> 3) & 0x70))

__device__ __forceinline__ void cp16(uint32_t dst, const void* src) {
    asm volatile("cp.async.cg.shared.global [%0], [%1], 16;" :: "r"(dst), "l"(src));
}
#define CP_COMMIT() asm volatile("cp.async.commit_group;" ::: "memory")
#define CP_WAIT1()  asm volatile("cp.async.wait_group 1;" ::: "memory")

__device__ __forceinline__ void ldsm_x4(uint32_t* r, uint32_t addr) {
    asm volatile("ldmatrix.sync.aligned.m8n8.x4.shared.b16 {%0,%1,%2,%3}, [%4];"
                 : "=r"(r[0]), "=r"(r[1]), "=r"(r[2]), "=r"(r[3]) : "r"(addr));
}
__device__ __forceinline__ void ldsm_x4_t(uint32_t* r, uint32_t addr) {
    asm volatile("ldmatrix.sync.aligned.m8n8.x4.trans.shared.b16 {%0,%1,%2,%3}, [%4];"
                 : "=r"(r[0]), "=r"(r[1]), "=r"(r[2]), "=r"(r[3]) : "r"(addr));
}

__device__ __forceinline__ void mma16816(float* c, const uint32_t* a, const uint32_t* b) {
    asm volatile("mma.sync.aligned.m16n8k16.row.col.f32.f16.f16.f32 "
                 "{%0,%1,%2,%3}, {%4,%5,%6,%7}, {%8,%9}, {%0,%1,%2,%3};"
                 : "+f"(c[0]), "+f"(c[1]), "+f"(c[2]), "+f"(c[3])
                 : "r"(a[0]), "r"(a[1]), "r"(a[2]), "r"(a[3]),
                   "r"(b[0]), "r"(b[1]));
}

__device__ __forceinline__ uint32_t pack_f16x2(float lo, float hi) {
    uint32_t u;
    asm("cvt.rn.f16x2.f32 %0, %1, %2;" : "=r"(u) : "f"(hi), "f"(lo));
    return u;
}

// exp(0.125*x) = ex2(x * 0.125*log2(e)) — one FMUL + one MUFU
__device__ __forceinline__ float exp_scaled(float x) {
    float r;
    asm("{ .reg .f32 t; mul.f32 t, %1, 0f3E38AA3B; ex2.approx.f32 %0, t; }"
        : "=f"(r) : "f"(x));
    return r;
}

// Async-load a 128-row x 64-half tile into SW128-swizzled SMEM.
template <int NTHR>
__device__ __forceinline__ void load_tile_async(uint32_t sdst, const __half* src,
                                                size_t rstride, int tid) {
    #pragma unroll
    for (int p = 0; p < 1024 / NTHR; p++) {
        int idx = tid + p * NTHR;           // 0..1023
        int row = idx >> 3, c8 = idx & 7;
        cp16(sdst + SWZ(row * 128 + c8 * 16), src + (size_t)row * rstride + c8 * 8);
    }
}

// ---------------------------------------------------------------------------
// fp32 -> fp16 conversion: x + w_qkv only (w_proj rides inside gemm0 — it is
// consumed first by gemm1, which launches after gemm0 completes).
// ---------------------------------------------------------------------------
#define NQ_X  ((MTOK * FDIM) / 4)        // 1048576
#define NQ_WQ ((HD3 * FDIM) / 4)         //  786432
#define NQ_WP ((FDIM * FDIM) / 4)        //  262144

__global__ __launch_bounds__(256) void f2h_xwq(
    const float* __restrict__ x, const float* __restrict__ wq,
    __half* __restrict__ xh, __half* __restrict__ wqh)
{
    int q = blockIdx.x * 256 + threadIdx.x;
    const float* s;
    __half* d;
    if (q < NQ_X) { s = x; d = xh; }
    else          { q -= NQ_X; s = wq; d = wqh; }
    int i = q * 4;
    float4 v = *(const float4*)(s + i);
    uint2 o;
    o.x = pack_f16x2(v.x, v.y);
    o.y = pack_f16x2(v.z, v.w);
    *(uint2*)(d + i) = o;
}

// ---------------------------------------------------------------------------
// HMMA GEMM (R8/R14 config — measured best): C[M,N] = A[M,K] @ B[N,K]^T.
// MODE 0: C fp16, plus piggy-back CTAs (blockIdx.x == gridDim.x-1) that
//         convert w_proj fp32->fp16 for the later gemm1 launch.
// MODE 1: C fp32 + bias.
// 128x128 CTA tile, BK=64, 8 warps (2m x 4n, 64x32 each).
// 3-stage cp.async, prefetch distance 2, one barrier per chunk; 2 CTA/SM.
// ---------------------------------------------------------------------------
#define GST   32768
#define GSMEM (3 * GST)

template <int MODE>
__global__ __launch_bounds__(256, 2) void gemm_mma(
    const __half* __restrict__ A, const __half* __restrict__ B,
    const float* __restrict__ bias, void* __restrict__ Cout,
    int M, int N, int K,
    const float* __restrict__ csrc, __half* __restrict__ cdst)
{
    if (MODE == 0 && blockIdx.x == gridDim.x - 1) {
        // Piggy-back convert CTAs: 16 CTAs x 256 threads x 64 float4 = w_proj.
        const int idx = blockIdx.y * 256 + threadIdx.x;   // 0..4095
        #pragma unroll 4
        for (int p = 0; p < 64; p++) {
            int i = (idx * 64 + p) * 4;
            float4 v = *(const float4*)(csrc + i);
            uint2 o;
            o.x = pack_f16x2(v.x, v.y);
            o.y = pack_f16x2(v.z, v.w);
            *(uint2*)(cdst + i) = o;
        }
        return;
    }

    extern __shared__ __align__(1024) char smem[];
    const uint32_t sb = smem_to_u32(smem);
    const int tid = threadIdx.x, wid = tid >> 5, lane = tid & 31;
    const int n0 = blockIdx.x * 128, m0 = blockIdx.y * 128;
    const int wm = (wid >> 2) * 64, wn = (wid & 3) * 32;

    const __half* Ab = A + (size_t)m0 * K;
    const __half* Bb = B + (size_t)n0 * K;

    #pragma unroll
    for (int s = 0; s < 2; s++) {
        load_tile_async<256>(sb + s * GST,         Ab + s * 64, K, tid);
        load_tile_async<256>(sb + s * GST + 16384, Bb + s * 64, K, tid);
        CP_COMMIT();
    }

    float acc[16][4];
    #pragma unroll
    for (int i = 0; i < 16; i++)
        #pragma unroll
        for (int j = 0; j < 4; j++) acc[i][j] = 0.f;

    const int nchunk = K >> 6;
    int srd = 0, swr = 2;
    for (int c = 0; c < nchunk; c++) {
        CP_WAIT1();
        __syncthreads();
        if (c + 2 < nchunk) {
            const uint32_t dst = sb + swr * GST;
            load_tile_async<256>(dst,         Ab + (c + 2) * 64, K, tid);
            load_tile_async<256>(dst + 16384, Bb + (c + 2) * 64, K, tid);
        }
        CP_COMMIT();

        const uint32_t sa = sb + srd * GST;
        const uint32_t sB = sa + 16384;
        #pragma unroll
        for (int ks = 0; ks < 4; ks++) {
            uint32_t a[4][4];
            #pragma unroll
            for (int mf = 0; mf < 4; mf++) {
                int row = wm + mf * 16 + (lane & 15);
                int cb  = ks * 32 + (lane >> 4) * 16;
                ldsm_x4(a[mf], sa + SWZ(row * 128 + cb));
            }
            #pragma unroll
            for (int ng = 0; ng < 2; ng++) {
                uint32_t bfr[4];
                int row = wn + ng * 16 + (lane & 7) + (lane >> 4) * 8;
                int cb  = ks * 32 + ((lane >> 3) & 1) * 16;
                ldsm_x4(bfr, sB + SWZ(row * 128 + cb));
                #pragma unroll
                for (int mf = 0; mf < 4; mf++) {
                    mma16816(acc[mf * 4 + 2 * ng],     a[mf], bfr);
                    mma16816(acc[mf * 4 + 2 * ng + 1], a[mf], bfr + 2);
                }
            }
        }
        srd = (srd == 2) ? 0 : srd + 1;
        swr = (swr == 2) ? 0 : swr + 1;
    }

    #pragma unroll
    for (int mf = 0; mf < 4; mf++) {
        const int r0 = m0 + wm + mf * 16 + (lane >> 2);
        #pragma unroll
        for (int nf = 0; nf < 4; nf++) {
            const int col = n0 + wn + nf * 8 + 2 * (lane & 3);
            const float* c = acc[mf * 4 + nf];
            if (MODE == 0) {
                __half* C = (__half*)Cout;
                *(uint32_t*)(C + (size_t)r0 * N + col)       = pack_f16x2(c[0], c[1]);
                *(uint32_t*)(C + (size_t)(r0 + 8) * N + col) = pack_f16x2(c[2], c[3]);
            } else {
                float* C = (float*)Cout;
                const float b0 = bias[col], b1 = bias[col + 1];
                float2 v0 = make_float2(c[0] + b0, c[1] + b1);
                float2 v1 = make_float2(c[2] + b0, c[3] + b1);
                *(float2*)(C + (size_t)r0 * N + col)       = v0;
                *(float2*)(C + (size_t)(r0 + 8) * N + col) = v1;
            }
        }
    }
}

// ---------------------------------------------------------------------------
// HMMA flash attention (R10 config — measured best): 128 queries / CTA,
// 4 warps x 32 rows, fp32-accum S, KV tile in four 32-key quarters with sacc
// double buffer (exp of quarter q overlaps S-mma of q+1). 3-stage KV cp.async
// pipeline, one barrier per tile. smem: Q 16K + 3x32K = 112 KB; 2 CTA/SM.
// ---------------------------------------------------------------------------
#define AKV   32768
#define ASMEM (16384 + 3 * AKV)

// S-mma for the HQ-th 32-key quarter: sq[2][4][4] = qf . K(quarter HQ)
template <int HQ>
__device__ __forceinline__ void s_quarter(float (*sq)[4][4],         // [mf][n8][4]
                                          const uint32_t (*qf)[4][4],
                                          uint32_t kbuf, int lane) {
    #pragma unroll
    for (int mf = 0; mf < 2; mf++)
        #pragma unroll
        for (int i = 0; i < 4; i++)
            #pragma unroll
            for (int j = 0; j < 4; j++) sq[mf][i][j] = 0.f;
    #pragma unroll
    for (int ks = 0; ks < 4; ks++) {
        #pragma unroll
        for (int ng = 0; ng < 2; ng++) {
            uint32_t bfr[4];
            int row = HQ * 32 + ng * 16 + (lane & 7) + (lane >> 4) * 8;
            int cb  = ks * 32 + ((lane >> 3) & 1) * 16;
            ldsm_x4(bfr, kbuf + SWZ(row * 128 + cb));
            #pragma unroll
            for (int mf = 0; mf < 2; mf++) {
                mma16816(sq[mf][2 * ng],     qf[mf][ks], bfr);
                mma16816(sq[mf][2 * ng + 1], qf[mf][ks], bfr + 2);
            }
        }
    }
}

__global__ __launch_bounds__(128, 2) void attn_mma(const __half* __restrict__ qkv,
                                                   __half* __restrict__ ao, int S)
{
    extern __shared__ __align__(1024) char smem[];
    const uint32_t sb = smem_to_u32(smem);
    const int tid = threadIdx.x, wid = tid >> 5, lane = tid & 31;
    const int q0 = blockIdx.x * 128, h = blockIdx.y, b = blockIdx.z;

    const __half* base = qkv + (size_t)(b * S) * HD3 + h * DHEAD;
    const __half* qptr = base + (size_t)q0 * HD3;
    const __half* kptr = base + FDIM;
    const __half* vptr = base + 2 * FDIM;

    load_tile_async<128>(sb,                 qptr, HD3, tid);
    load_tile_async<128>(sb + 16384,         kptr, HD3, tid);
    load_tile_async<128>(sb + 16384 + 16384, vptr, HD3, tid);
    CP_COMMIT();
    load_tile_async<128>(sb + 16384 + AKV,         kptr + (size_t)128 * HD3, HD3, tid);
    load_tile_async<128>(sb + 16384 + AKV + 16384, vptr + (size_t)128 * HD3, HD3, tid);
    CP_COMMIT();

    CP_WAIT1();
    __syncthreads();

    // Resident Q fragments: 2 m16 frags x 4 k-steps x 4 regs = 32 regs
    uint32_t qf[2][4][4];
    #pragma unroll
    for (int mf = 0; mf < 2; mf++)
        #pragma unroll
        for (int ks = 0; ks < 4; ks++) {
            int row = wid * 32 + mf * 16 + (lane & 15);
            int cb  = ks * 32 + (lane >> 4) * 16;
            ldsm_x4(qf[mf][ks], sb + SWZ(row * 128 + cb));
        }

    float O[2][8][4];
    #pragma unroll
    for (int mf = 0; mf < 2; mf++)
        #pragma unroll
        for (int i = 0; i < 8; i++)
            #pragma unroll
            for (int j = 0; j < 4; j++) O[mf][i][j] = 0.f;
    float lsum[2][2] = {{0.f, 0.f}, {0.f, 0.f}};

    float sbuf[2][2][4][4];   // [buf][mf][n8-tile][reg] — one 32-key quarter each

    const int NT = S >> 7;   // 16
    int srd = 0, swr = 2;
    for (int t = 0; t < NT; t++) {
        if (t > 0) { CP_WAIT1(); __syncthreads(); }
        if (t + 2 < NT) {
            const uint32_t dst = sb + 16384 + swr * AKV;
            load_tile_async<128>(dst,         kptr + (size_t)(t + 2) * 128 * HD3, HD3, tid);
            load_tile_async<128>(dst + 16384, vptr + (size_t)(t + 2) * 128 * HD3, HD3, tid);
        }
        CP_COMMIT();

        const uint32_t kbuf = sb + 16384 + srd * AKV;
        const uint32_t vbuf = kbuf + 16384;

        s_quarter<0>(sbuf[0], qf, kbuf, lane);
        #pragma unroll
        for (int qq = 0; qq < 4; qq++) {
            const int bi = qq & 1;

            // exp + pack -> P a-frags (MUFU; overlaps next quarter's S-mma)
            uint32_t P[2][2][4];
            #pragma unroll
            for (int mf = 0; mf < 2; mf++)
                #pragma unroll
                for (int g = 0; g < 2; g++) {
                    const float* c0 = sbuf[bi][mf][2 * g];
                    const float* c1 = sbuf[bi][mf][2 * g + 1];
                    float e00 = exp_scaled(c0[0]), e01 = exp_scaled(c0[1]);
                    float e02 = exp_scaled(c0[2]), e03 = exp_scaled(c0[3]);
                    float e10 = exp_scaled(c1[0]), e11 = exp_scaled(c1[1]);
                    float e12 = exp_scaled(c1[2]), e13 = exp_scaled(c1[3]);
                    lsum[mf][0] += e00 + e01 + e10 + e11;
                    lsum[mf][1] += e02 + e03 + e12 + e13;
                    P[mf][g][0] = pack_f16x2(e00, e01);
                    P[mf][g][1] = pack_f16x2(e02, e03);
                    P[mf][g][2] = pack_f16x2(e10, e11);
                    P[mf][g][3] = pack_f16x2(e12, e13);
                }

            if (qq == 0)      s_quarter<1>(sbuf[1], qf, kbuf, lane);
            else if (qq == 1) s_quarter<2>(sbuf[0], qf, kbuf, lane);
            else if (qq == 2) s_quarter<3>(sbuf[1], qf, kbuf, lane);

            // O += P @ V for this quarter (2 k16-steps over 32 keys)
            #pragma unroll
            for (int ks2 = 0; ks2 < 2; ks2++) {
                #pragma unroll
                for (int dg = 0; dg < 4; dg++) {
                    uint32_t vfr[4];
                    int row = qq * 32 + ks2 * 16 + (lane & 7) + ((lane >> 3) & 1) * 8;
                    int cb  = dg * 32 + (lane >> 4) * 16;
                    ldsm_x4_t(vfr, vbuf + SWZ(row * 128 + cb));
                    #pragma unroll
                    for (int mf = 0; mf < 2; mf++) {
                        mma16816(O[mf][2 * dg],     P[mf][ks2], vfr);
                        mma16816(O[mf][2 * dg + 1], P[mf][ks2], vfr + 2);
                    }
                }
            }
        }

        srd = (srd == 2) ? 0 : srd + 1;
        swr = (swr == 2) ? 0 : swr + 1;
    }

    // Row-sum reduction across the quad, normalize, store
    __half* aop = ao + (size_t)(b * S) * FDIM + h * DHEAD;
    #pragma unroll
    for (int mf = 0; mf < 2; mf++) {
        float l0 = lsum[mf][0], l1 = lsum[mf][1];
        l0 += __shfl_xor_sync(0xffffffffu, l0, 1);
        l0 += __shfl_xor_sync(0xffffffffu, l0, 2);
        l1 += __shfl_xor_sync(0xffffffffu, l1, 1);
        l1 += __shfl_xor_sync(0xffffffffu, l1, 2);
        const float inv0 = 1.f / l0, inv1 = 1.f / l1;
        const int r0 = q0 + wid * 32 + mf * 16 + (lane >> 2);
        #pragma unroll
        for (int nf = 0; nf < 8; nf++) {
            const int col = nf * 8 + 2 * (lane & 3);
            *(uint32_t*)(aop + (size_t)r0 * FDIM + col) =
                pack_f16x2(O[mf][nf][0] * inv0, O[mf][nf][1] * inv0);
            *(uint32_t*)(aop + (size_t)(r0 + 8) * FDIM + col) =
                pack_f16x2(O[mf][nf][2] * inv1, O[mf][nf][3] * inv1);
        }
    }
}

// ---------------------------------------------------------------------------
extern "C" void kernel_launch(void* const* d_in, const int* in_sizes, int n_in,
                              void* d_out, int out_size)
{
    const float* x      = (const float*)d_in[0];
    const float* w_qkv  = (const float*)d_in[1];
    const float* w_proj = (const float*)d_in[2];
    const float* b_proj = (const float*)d_in[3];
    float* out = (float*)d_out;

    const int M = in_sizes[0] / FDIM;   // 4096
    const int S = SEQ;
    const int B = M / S;

    __half *xh, *wqh, *wph, *qh, *aoh;
    cudaGetSymbolAddress((void**)&xh,  g_xh);
    cudaGetSymbolAddress((void**)&wqh, g_wqkvh);
    cudaGetSymbolAddress((void**)&wph, g_wprojh);
    cudaGetSymbolAddress((void**)&qh,  g_qkvh);
    cudaGetSymbolAddress((void**)&aoh, g_aoh);

    cudaFuncSetAttribute(gemm_mma<0>, cudaFuncAttributeMaxDynamicSharedMemorySize, GSMEM);
    cudaFuncSetAttribute(gemm_mma<1>, cudaFuncAttributeMaxDynamicSharedMemorySize, GSMEM);
    cudaFuncSetAttribute(attn_mma,    cudaFuncAttributeMaxDynamicSharedMemorySize, ASMEM);

    // fp32 -> fp16 for x + w_qkv only (w_proj converts inside gemm0's launch)
    f2h_xwq<<<(NQ_X + NQ_WQ) / 256, 256>>>(x, w_qkv, xh, wqh);

    // 1) QKV projection; last grid column (16 CTAs) converts w_proj for gemm1
    gemm_mma<0><<<dim3(HD3 / 128 + 1, M / 128), 256, GSMEM>>>(
        xh, wqh, nullptr, qh, M, HD3, FDIM, w_proj, wph);

    // 2) Attention (fp32-accum S — best accuracy at the roofline)
    attn_mma<<<dim3(S / 128, NHEADS, B), 128, ASMEM>>>(qh, aoh, S);

    // 3) Output projection
    gemm_mma<1><<<dim3(FDIM / 128, M / 128), 256, GSMEM>>>(
        aoh, wph, b_proj, out, M, FDIM, FDIM, nullptr, nullptr);
}

// round 16
// speedup vs baseline: 1.0265x; 1.0265x over previous
#include <cuda_runtime.h>
#include <cuda_fp16.h>
#include <cstdint>
#include <cstddef>

#define FDIM   1024
#define HD3    3072
#define NHEADS 16
#define DHEAD  64
#define MTOK   4096
#define SEQ    2048

// ---------------------------------------------------------------------------
// Scratch (__device__ globals per allocation rules)
// ---------------------------------------------------------------------------
__device__ __half g_xh    [(size_t)MTOK * FDIM];
__device__ __half g_wqkvh [(size_t)HD3  * FDIM];
__device__ __half g_wprojh[(size_t)FDIM * FDIM];
__device__ __half g_qkvh  [(size_t)MTOK * HD3];
__device__ __half g_aoh   [(size_t)MTOK * FDIM];

// ---------------------------------------------------------------------------
// Helpers: base-sm_103-safe ISA only (mma.sync / ldmatrix / cp.async)
// ---------------------------------------------------------------------------
__device__ __forceinline__ uint32_t smem_to_u32(const void* p) {
    uint32_t a;
    asm("{ .reg .u64 t; cvta.to.shared.u64 t, %1; cvt.u32.u64 %0, t; }" : "=r"(a) : "l"(p));
    return a;
}

#define SWZ(off) ((uint32_t)(off) ^ ((((uint32_t)(off)) >> 3) & 0x70))

__device__ __forceinline__ void cp16(uint32_t dst, const void* src) {
    asm volatile("cp.async.cg.shared.global [%0], [%1], 16;" :: "r"(dst), "l"(src));
}
#define CP_COMMIT() asm volatile("cp.async.commit_group;" ::: "memory")
#define CP_WAIT1()  asm volatile("cp.async.wait_group 1;" ::: "memory")

__device__ __forceinline__ void ldsm_x4(uint32_t* r, uint32_t addr) {
    asm volatile("ldmatrix.sync.aligned.m8n8.x4.shared.b16 {%0,%1,%2,%3}, [%4];"
                 : "=r"(r[0]), "=r"(r[1]), "=r"(r[2]), "=r"(r[3]) : "r"(addr));
}
__device__ __forceinline__ void ldsm_x4_t(uint32_t* r, uint32_t addr) {
    asm volatile("ldmatrix.sync.aligned.m8n8.x4.trans.shared.b16 {%0,%1,%2,%3}, [%4];"
                 : "=r"(r[0]), "=r"(r[1]), "=r"(r[2]), "=r"(r[3]) : "r"(addr));
}

__device__ __forceinline__ void mma16816(float* c, const uint32_t* a, const uint32_t* b) {
    asm volatile("mma.sync.aligned.m16n8k16.row.col.f32.f16.f16.f32 "
                 "{%0,%1,%2,%3}, {%4,%5,%6,%7}, {%8,%9}, {%0,%1,%2,%3};"
                 : "+f"(c[0]), "+f"(c[1]), "+f"(c[2]), "+f"(c[3])
                 : "r"(a[0]), "r"(a[1]), "r"(a[2]), "r"(a[3]),
                   "r"(b[0]), "r"(b[1]));
}

__device__ __forceinline__ uint32_t pack_f16x2(float lo, float hi) {
    uint32_t u;
    asm("cvt.rn.f16x2.f32 %0, %1, %2;" : "=r"(u) : "f"(hi), "f"(lo));
    return u;
}

// exp(0.125*x) = ex2(x * 0.125*log2(e)) — one FMUL + one MUFU
__device__ __forceinline__ float exp_scaled(float x) {
    float r;
    asm("{ .reg .f32 t; mul.f32 t, %1, 0f3E38AA3B; ex2.approx.f32 %0, t; }"
        : "=f"(r) : "f"(x));
    return r;
}

// Async-load a 128-row x 64-half tile into SW128-swizzled SMEM.
template <int NTHR>
__device__ __forceinline__ void load_tile_async(uint32_t sdst, const __half* src,
                                                size_t rstride, int tid) {
    #pragma unroll
    for (int p = 0; p < 1024 / NTHR; p++) {
        int idx = tid + p * NTHR;           // 0..1023
        int row = idx >> 3, c8 = idx & 7;
        cp16(sdst + SWZ(row * 128 + c8 * 16), src + (size_t)row * rstride + c8 * 8);
    }
}

// ---------------------------------------------------------------------------
// fp32 -> fp16 conversion, all three tensors in one launch
// ---------------------------------------------------------------------------
#define NQ_X  ((MTOK * FDIM) / 4)        // 1048576
#define NQ_WQ ((HD3 * FDIM) / 4)         //  786432
#define NQ_WP ((FDIM * FDIM) / 4)        //  262144

__global__ __launch_bounds__(256) void f2h_all(
    const float* __restrict__ x, const float* __restrict__ wq,
    const float* __restrict__ wp,
    __half* __restrict__ xh, __half* __restrict__ wqh, __half* __restrict__ wph)
{
    int q = blockIdx.x * 256 + threadIdx.x;
    const float* s;
    __half* d;
    if (q < NQ_X)                { s = x;  d = xh; }
    else if (q < NQ_X + NQ_WQ)   { q -= NQ_X;         s = wq; d = wqh; }
    else                         { q -= NQ_X + NQ_WQ; s = wp; d = wph; }
    int i = q * 4;
    float4 v = *(const float4*)(s + i);
    uint2 o;
    o.x = pack_f16x2(v.x, v.y);
    o.y = pack_f16x2(v.z, v.w);
    *(uint2*)(d + i) = o;
}

// ---------------------------------------------------------------------------
// HMMA GEMM (R8 config — measured best): C[M,N] = A[M,K] @ B[N,K]^T.
// MODE 0: C fp16.  MODE 1: C fp32 + bias.
// 128x128 CTA tile, BK=64, 8 warps (2m x 4n, 64x32 each).
// 3-stage cp.async, prefetch distance 2, one barrier per chunk; 2 CTA/SM.
// ---------------------------------------------------------------------------
#define GST   32768
#define GSMEM (3 * GST)

template <int MODE>
__global__ __launch_bounds__(256, 2) void gemm_mma(
    const __half* __restrict__ A, const __half* __restrict__ B,
    const float* __restrict__ bias, void* __restrict__ Cout,
    int M, int N, int K)
{
    extern __shared__ __align__(1024) char smem[];
    const uint32_t sb = smem_to_u32(smem);
    const int tid = threadIdx.x, wid = tid >> 5, lane = tid & 31;
    const int n0 = blockIdx.x * 128, m0 = blockIdx.y * 128;
    const int wm = (wid >> 2) * 64, wn = (wid & 3) * 32;

    const __half* Ab = A + (size_t)m0 * K;
    const __half* Bb = B + (size_t)n0 * K;

    #pragma unroll
    for (int s = 0; s < 2; s++) {
        load_tile_async<256>(sb + s * GST,         Ab + s * 64, K, tid);
        load_tile_async<256>(sb + s * GST + 16384, Bb + s * 64, K, tid);
        CP_COMMIT();
    }

    float acc[16][4];
    #pragma unroll
    for (int i = 0; i < 16; i++)
        #pragma unroll
        for (int j = 0; j < 4; j++) acc[i][j] = 0.f;

    const int nchunk = K >> 6;
    int srd = 0, swr = 2;
    for (int c = 0; c < nchunk; c++) {
        CP_WAIT1();
        __syncthreads();
        if (c + 2 < nchunk) {
            const uint32_t dst = sb + swr * GST;
            load_tile_async<256>(dst,         Ab + (c + 2) * 64, K, tid);
            load_tile_async<256>(dst + 16384, Bb + (c + 2) * 64, K, tid);
        }
        CP_COMMIT();

        const uint32_t sa = sb + srd * GST;
        const uint32_t sB = sa + 16384;
        #pragma unroll
        for (int ks = 0; ks < 4; ks++) {
            uint32_t a[4][4];
            #pragma unroll
            for (int mf = 0; mf < 4; mf++) {
                int row = wm + mf * 16 + (lane & 15);
                int cb  = ks * 32 + (lane >> 4) * 16;
                ldsm_x4(a[mf], sa + SWZ(row * 128 + cb));
            }
            #pragma unroll
            for (int ng = 0; ng < 2; ng++) {
                uint32_t bfr[4];
                int row = wn + ng * 16 + (lane & 7) + (lane >> 4) * 8;
                int cb  = ks * 32 + ((lane >> 3) & 1) * 16;
                ldsm_x4(bfr, sB + SWZ(row * 128 + cb));
                #pragma unroll
                for (int mf = 0; mf < 4; mf++) {
                    mma16816(acc[mf * 4 + 2 * ng],     a[mf], bfr);
                    mma16816(acc[mf * 4 + 2 * ng + 1], a[mf], bfr + 2);
                }
            }
        }
        srd = (srd == 2) ? 0 : srd + 1;
        swr = (swr == 2) ? 0 : swr + 1;
    }

    #pragma unroll
    for (int mf = 0; mf < 4; mf++) {
        const int r0 = m0 + wm + mf * 16 + (lane >> 2);
        #pragma unroll
        for (int nf = 0; nf < 4; nf++) {
            const int col = n0 + wn + nf * 8 + 2 * (lane & 3);
            const float* c = acc[mf * 4 + nf];
            if (MODE == 0) {
                __half* C = (__half*)Cout;
                *(uint32_t*)(C + (size_t)r0 * N + col)       = pack_f16x2(c[0], c[1]);
                *(uint32_t*)(C + (size_t)(r0 + 8) * N + col) = pack_f16x2(c[2], c[3]);
            } else {
                float* C = (float*)Cout;
                const float b0 = bias[col], b1 = bias[col + 1];
                float2 v0 = make_float2(c[0] + b0, c[1] + b1);
                float2 v1 = make_float2(c[2] + b0, c[3] + b1);
                *(float2*)(C + (size_t)r0 * N + col)       = v0;
                *(float2*)(C + (size_t)(r0 + 8) * N + col) = v1;
            }
        }
    }
}

// ---------------------------------------------------------------------------
// HMMA flash attention (R10 config — measured best): 128 queries / CTA,
// 4 warps x 32 rows, fp32-accum S, KV tile in four 32-key quarters with sacc
// double buffer (exp of quarter q overlaps S-mma of q+1). 3-stage KV cp.async
// pipeline, one barrier per tile. smem: Q 16K + 3x32K = 112 KB; 2 CTA/SM.
// ---------------------------------------------------------------------------
#define AKV   32768
#define ASMEM (16384 + 3 * AKV)

// S-mma for the HQ-th 32-key quarter: sq[2][4][4] = qf . K(quarter HQ)
template <int HQ>
__device__ __forceinline__ void s_quarter(float (*sq)[4][4],         // [mf][n8][4]
                                          const uint32_t (*qf)[4][4],
                                          uint32_t kbuf, int lane) {
    #pragma unroll
    for (int mf = 0; mf < 2; mf++)
        #pragma unroll
        for (int i = 0; i < 4; i++)
            #pragma unroll
            for (int j = 0; j < 4; j++) sq[mf][i][j] = 0.f;
    #pragma unroll
    for (int ks = 0; ks < 4; ks++) {
        #pragma unroll
        for (int ng = 0; ng < 2; ng++) {
            uint32_t bfr[4];
            int row = HQ * 32 + ng * 16 + (lane & 7) + (lane >> 4) * 8;
            int cb  = ks * 32 + ((lane >> 3) & 1) * 16;
            ldsm_x4(bfr, kbuf + SWZ(row * 128 + cb));
            #pragma unroll
            for (int mf = 0; mf < 2; mf++) {
                mma16816(sq[mf][2 * ng],     qf[mf][ks], bfr);
                mma16816(sq[mf][2 * ng + 1], qf[mf][ks], bfr + 2);
            }
        }
    }
}

__global__ __launch_bounds__(128, 2) void attn_mma(const __half* __restrict__ qkv,
                                                   __half* __restrict__ ao, int S)
{
    extern __shared__ __align__(1024) char smem[];
    const uint32_t sb = smem_to_u32(smem);
    const int tid = threadIdx.x, wid = tid >> 5, lane = tid & 31;
    const int q0 = blockIdx.x * 128, h = blockIdx.y, b = blockIdx.z;

    const __half* base = qkv + (size_t)(b * S) * HD3 + h * DHEAD;
    const __half* qptr = base + (size_t)q0 * HD3;
    const __half* kptr = base + FDIM;
    const __half* vptr = base + 2 * FDIM;

    load_tile_async<128>(sb,                 qptr, HD3, tid);
    load_tile_async<128>(sb + 16384,         kptr, HD3, tid);
    load_tile_async<128>(sb + 16384 + 16384, vptr, HD3, tid);
    CP_COMMIT();
    load_tile_async<128>(sb + 16384 + AKV,         kptr + (size_t)128 * HD3, HD3, tid);
    load_tile_async<128>(sb + 16384 + AKV + 16384, vptr + (size_t)128 * HD3, HD3, tid);
    CP_COMMIT();

    CP_WAIT1();
    __syncthreads();

    // Resident Q fragments: 2 m16 frags x 4 k-steps x 4 regs = 32 regs
    uint32_t qf[2][4][4];
    #pragma unroll
    for (int mf = 0; mf < 2; mf++)
        #pragma unroll
        for (int ks = 0; ks < 4; ks++) {
            int row = wid * 32 + mf * 16 + (lane & 15);
            int cb  = ks * 32 + (lane >> 4) * 16;
            ldsm_x4(qf[mf][ks], sb + SWZ(row * 128 + cb));
        }

    float O[2][8][4];
    #pragma unroll
    for (int mf = 0; mf < 2; mf++)
        #pragma unroll
        for (int i = 0; i < 8; i++)
            #pragma unroll
            for (int j = 0; j < 4; j++) O[mf][i][j] = 0.f;
    float lsum[2][2] = {{0.f, 0.f}, {0.f, 0.f}};

    float sbuf[2][2][4][4];   // [buf][mf][n8-tile][reg] — one 32-key quarter each

    const int NT = S >> 7;   // 16
    int srd = 0, swr = 2;
    for (int t = 0; t < NT; t++) {
        if (t > 0) { CP_WAIT1(); __syncthreads(); }
        if (t + 2 < NT) {
            const uint32_t dst = sb + 16384 + swr * AKV;
            load_tile_async<128>(dst,         kptr + (size_t)(t + 2) * 128 * HD3, HD3, tid);
            load_tile_async<128>(dst + 16384, vptr + (size_t)(t + 2) * 128 * HD3, HD3, tid);
        }
        CP_COMMIT();

        const uint32_t kbuf = sb + 16384 + srd * AKV;
        const uint32_t vbuf = kbuf + 16384;

        s_quarter<0>(sbuf[0], qf, kbuf, lane);
        #pragma unroll
        for (int qq = 0; qq < 4; qq++) {
            const int bi = qq & 1;

            // exp + pack -> P a-frags (MUFU; overlaps next quarter's S-mma)
            uint32_t P[2][2][4];
            #pragma unroll
            for (int mf = 0; mf < 2; mf++)
                #pragma unroll
                for (int g = 0; g < 2; g++) {
                    const float* c0 = sbuf[bi][mf][2 * g];
                    const float* c1 = sbuf[bi][mf][2 * g + 1];
                    float e00 = exp_scaled(c0[0]), e01 = exp_scaled(c0[1]);
                    float e02 = exp_scaled(c0[2]), e03 = exp_scaled(c0[3]);
                    float e10 = exp_scaled(c1[0]), e11 = exp_scaled(c1[1]);
                    float e12 = exp_scaled(c1[2]), e13 = exp_scaled(c1[3]);
                    lsum[mf][0] += e00 + e01 + e10 + e11;
                    lsum[mf][1] += e02 + e03 + e12 + e13;
                    P[mf][g][0] = pack_f16x2(e00, e01);
                    P[mf][g][1] = pack_f16x2(e02, e03);
                    P[mf][g][2] = pack_f16x2(e10, e11);
                    P[mf][g][3] = pack_f16x2(e12, e13);
                }

            if (qq == 0)      s_quarter<1>(sbuf[1], qf, kbuf, lane);
            else if (qq == 1) s_quarter<2>(sbuf[0], qf, kbuf, lane);
            else if (qq == 2) s_quarter<3>(sbuf[1], qf, kbuf, lane);

            // O += P @ V for this quarter (2 k16-steps over 32 keys)
            #pragma unroll
            for (int ks2 = 0; ks2 < 2; ks2++) {
                #pragma unroll
                for (int dg = 0; dg < 4; dg++) {
                    uint32_t vfr[4];
                    int row = qq * 32 + ks2 * 16 + (lane & 7) + ((lane >> 3) & 1) * 8;
                    int cb  = dg * 32 + (lane >> 4) * 16;
                    ldsm_x4_t(vfr, vbuf + SWZ(row * 128 + cb));
                    #pragma unroll
                    for (int mf = 0; mf < 2; mf++) {
                        mma16816(O[mf][2 * dg],     P[mf][ks2], vfr);
                        mma16816(O[mf][2 * dg + 1], P[mf][ks2], vfr + 2);
                    }
                }
            }
        }

        srd = (srd == 2) ? 0 : srd + 1;
        swr = (swr == 2) ? 0 : swr + 1;
    }

    // Row-sum reduction across the quad, normalize, store
    __half* aop = ao + (size_t)(b * S) * FDIM + h * DHEAD;
    #pragma unroll
    for (int mf = 0; mf < 2; mf++) {
        float l0 = lsum[mf][0], l1 = lsum[mf][1];
        l0 += __shfl_xor_sync(0xffffffffu, l0, 1);
        l0 += __shfl_xor_sync(0xffffffffu, l0, 2);
        l1 += __shfl_xor_sync(0xffffffffu, l1, 1);
        l1 += __shfl_xor_sync(0xffffffffu, l1, 2);
        const float inv0 = 1.f / l0, inv1 = 1.f / l1;
        const int r0 = q0 + wid * 32 + mf * 16 + (lane >> 2);
        #pragma unroll
        for (int nf = 0; nf < 8; nf++) {
            const int col = nf * 8 + 2 * (lane & 3);
            *(uint32_t*)(aop + (size_t)r0 * FDIM + col) =
                pack_f16x2(O[mf][nf][0] * inv0, O[mf][nf][1] * inv0);
            *(uint32_t*)(aop + (size_t)(r0 + 8) * FDIM + col) =
                pack_f16x2(O[mf][nf][2] * inv1, O[mf][nf][3] * inv1);
        }
    }
}

// ---------------------------------------------------------------------------
extern "C" void kernel_launch(void* const* d_in, const int* in_sizes, int n_in,
                              void* d_out, int out_size)
{
    const float* x      = (const float*)d_in[0];
    const float* w_qkv  = (const float*)d_in[1];
    const float* w_proj = (const float*)d_in[2];
    const float* b_proj = (const float*)d_in[3];
    float* out = (float*)d_out;

    const int M = in_sizes[0] / FDIM;   // 4096
    const int S = SEQ;
    const int B = M / S;

    __half *xh, *wqh, *wph, *qh, *aoh;
    cudaGetSymbolAddress((void**)&xh,  g_xh);
    cudaGetSymbolAddress((void**)&wqh, g_wqkvh);
    cudaGetSymbolAddress((void**)&wph, g_wprojh);
    cudaGetSymbolAddress((void**)&qh,  g_qkvh);
    cudaGetSymbolAddress((void**)&aoh, g_aoh);

    cudaFuncSetAttribute(gemm_mma<0>, cudaFuncAttributeMaxDynamicSharedMemorySize, GSMEM);
    cudaFuncSetAttribute(gemm_mma<1>, cudaFuncAttributeMaxDynamicSharedMemorySize, GSMEM);
    cudaFuncSetAttribute(attn_mma,    cudaFuncAttributeMaxDynamicSharedMemorySize, ASMEM);

    f2h_all<<<(NQ_X + NQ_WQ + NQ_WP + 255) / 256, 256>>>(x, w_qkv, w_proj, xh, wqh, wph);

    // 1) QKV projection
    gemm_mma<0><<<dim3(HD3 / 128, M / 128), 256, GSMEM>>>(xh, wqh, nullptr, qh, M, HD3, FDIM);

    // 2) Attention (fp32-accum S — best accuracy at the roofline)
    attn_mma<<<dim3(S / 128, NHEADS, B), 128, ASMEM>>>(qh, aoh, S);

    // 3) Output projection
    gemm_mma<1><<<dim3(FDIM / 128, M / 128), 256, GSMEM>>>(aoh, wph, b_proj, out, M, FDIM, FDIM);
}